// round 3
// baseline (speedup 1.0000x reference)
#include <cuda_runtime.h>
#include <cstdint>

#define NEG_SLOPE 0.01f

// ---------------------------------------------------------------------------
// Problem constants
// ---------------------------------------------------------------------------
#define NN   65536      // nodes
#define EE   262144     // edges
#define DIN  128        // node-MLP output dim
#define DNODE 256       // node input feature dim (2*DIN)
#define DEDGE 272       // edge-MLP input dim (2*DIN + 16)
#define HID  256
#define EA   16
#define NOUT 3

// ---------------------------------------------------------------------------
// Scratch (device globals: allocation is forbidden)
// ---------------------------------------------------------------------------
static __device__ float g_hnode[(size_t)NN * DIN];     // 32 MB
static __device__ float g_hA[(size_t)EE * HID];        // 256 MB
static __device__ float g_hB[(size_t)EE * HID];        // 256 MB

__device__ __forceinline__ float lrelu(float v) {
    return v >= 0.0f ? v : NEG_SLOPE * v;
}

// ---------------------------------------------------------------------------
// Generic tiled SGEMM:  C[M,N] = leaky(A[M,K] @ B[K,N] + bias[N])
// BM=BN=128, BK=8, 256 threads, 8x8 register tile per thread.
// Requires M%128==0, N%128==0, K%8==0 (true for all our shapes).
// ---------------------------------------------------------------------------
__global__ __launch_bounds__(256)
void sgemm_bias_leaky(const float* __restrict__ A,
                      const float* __restrict__ B,
                      const float* __restrict__ bias,
                      float* __restrict__ C,
                      int M, int N, int K)
{
    __shared__ float As[8][128];
    __shared__ float Bs[8][128];

    const int t        = threadIdx.x;
    const int blockRow = blockIdx.x * 128;
    const int blockCol = blockIdx.y * 128;

    // A-tile load map: 128 rows x 8 k  -> one float4 per thread
    const int aRow = t >> 1;
    const int aK   = (t & 1) * 4;
    // B-tile load map: 8 k x 128 cols -> one float4 per thread
    const int bK   = t >> 5;
    const int bN   = (t & 31) * 4;

    // compute map: 16x16 threads, each 8x8 outputs
    const int tr = t >> 4;
    const int tc = t & 15;

    float acc[8][8];
#pragma unroll
    for (int i = 0; i < 8; i++)
#pragma unroll
        for (int j = 0; j < 8; j++) acc[i][j] = 0.0f;

    for (int k0 = 0; k0 < K; k0 += 8) {
        float4 av = *(const float4*)(A + (size_t)(blockRow + aRow) * K + k0 + aK);
        As[aK + 0][aRow] = av.x;
        As[aK + 1][aRow] = av.y;
        As[aK + 2][aRow] = av.z;
        As[aK + 3][aRow] = av.w;
        *(float4*)&Bs[bK][bN] =
            *(const float4*)(B + (size_t)(k0 + bK) * N + blockCol + bN);
        __syncthreads();

#pragma unroll
        for (int k = 0; k < 8; k++) {
            float ra[8], rb[8];
            *(float4*)&ra[0] = *(const float4*)&As[k][tr * 8];
            *(float4*)&ra[4] = *(const float4*)&As[k][tr * 8 + 4];
            *(float4*)&rb[0] = *(const float4*)&Bs[k][tc * 8];
            *(float4*)&rb[4] = *(const float4*)&Bs[k][tc * 8 + 4];
#pragma unroll
            for (int i = 0; i < 8; i++)
#pragma unroll
                for (int j = 0; j < 8; j++)
                    acc[i][j] = fmaf(ra[i], rb[j], acc[i][j]);
        }
        __syncthreads();
    }

#pragma unroll
    for (int i = 0; i < 8; i++) {
        const size_t rrow = (size_t)(blockRow + tr * 8 + i);
#pragma unroll
        for (int j = 0; j < 8; j += 4) {
            const int cc = blockCol + tc * 8 + j;
            float4 o;
            o.x = lrelu(acc[i][j + 0] + bias[cc + 0]);
            o.y = lrelu(acc[i][j + 1] + bias[cc + 1]);
            o.z = lrelu(acc[i][j + 2] + bias[cc + 2]);
            o.w = lrelu(acc[i][j + 3] + bias[cc + 3]);
            *(float4*)(C + rrow * N + cc) = o;
        }
    }
}

// ---------------------------------------------------------------------------
// Edge layer 0: h0 = leaky( [hnode[row] | hnode[col] | eattr] @ W0 + b0 )
// Same tiling; A tile is gathered on the fly (K=272 = 34 * 8).
// edge_index is INT32 (JAX x64-disabled downcasts the requested int64).
// ---------------------------------------------------------------------------
__global__ __launch_bounds__(256)
void edge0_gemm(const float* __restrict__ hnode,
                const int* __restrict__ eidx,         // [2, E] int32
                const float* __restrict__ eattr,      // [E, 16]
                const float* __restrict__ W0,         // [272, 256]
                const float* __restrict__ b0,         // [256]
                float* __restrict__ C)                // [E, 256]
{
    const int N = HID, K = DEDGE;
    __shared__ float As[8][128];
    __shared__ float Bs[8][128];
    __shared__ int   rs[128];
    __shared__ int   cs[128];

    const int t        = threadIdx.x;
    const int blockRow = blockIdx.x * 128;
    const int blockCol = blockIdx.y * 128;

    if (t < 128) rs[t] = eidx[blockRow + t];
    else         cs[t - 128] = eidx[EE + blockRow + (t - 128)];
    __syncthreads();

    const int aRow = t >> 1;
    const int aK   = (t & 1) * 4;
    const int bK   = t >> 5;
    const int bN   = (t & 31) * 4;
    const int tr   = t >> 4;
    const int tc   = t & 15;

    float acc[8][8];
#pragma unroll
    for (int i = 0; i < 8; i++)
#pragma unroll
        for (int j = 0; j < 8; j++) acc[i][j] = 0.0f;

    for (int k0 = 0; k0 < K; k0 += 8) {
        const int k = k0 + aK;
        float4 av;
        if (k < 128)
            av = *(const float4*)(hnode + (size_t)rs[aRow] * DIN + k);
        else if (k < 256)
            av = *(const float4*)(hnode + (size_t)cs[aRow] * DIN + (k - 128));
        else
            av = *(const float4*)(eattr + (size_t)(blockRow + aRow) * EA + (k - 256));
        As[aK + 0][aRow] = av.x;
        As[aK + 1][aRow] = av.y;
        As[aK + 2][aRow] = av.z;
        As[aK + 3][aRow] = av.w;
        *(float4*)&Bs[bK][bN] =
            *(const float4*)(W0 + (size_t)(k0 + bK) * N + blockCol + bN);
        __syncthreads();

#pragma unroll
        for (int kk = 0; kk < 8; kk++) {
            float ra[8], rb[8];
            *(float4*)&ra[0] = *(const float4*)&As[kk][tr * 8];
            *(float4*)&ra[4] = *(const float4*)&As[kk][tr * 8 + 4];
            *(float4*)&rb[0] = *(const float4*)&Bs[kk][tc * 8];
            *(float4*)&rb[4] = *(const float4*)&Bs[kk][tc * 8 + 4];
#pragma unroll
            for (int i = 0; i < 8; i++)
#pragma unroll
                for (int j = 0; j < 8; j++)
                    acc[i][j] = fmaf(ra[i], rb[j], acc[i][j]);
        }
        __syncthreads();
    }

#pragma unroll
    for (int i = 0; i < 8; i++) {
        const size_t rrow = (size_t)(blockRow + tr * 8 + i);
#pragma unroll
        for (int j = 0; j < 8; j += 4) {
            const int cc = blockCol + tc * 8 + j;
            float4 o;
            o.x = lrelu(acc[i][j + 0] + b0[cc + 0]);
            o.y = lrelu(acc[i][j + 1] + b0[cc + 1]);
            o.z = lrelu(acc[i][j + 2] + b0[cc + 2]);
            o.w = lrelu(acc[i][j + 3] + b0[cc + 3]);
            *(float4*)(C + rrow * N + cc) = o;
        }
    }
}

// ---------------------------------------------------------------------------
// Head: logits = h @ Wlast + blast  -> log_softmax.  One warp per edge.
// ---------------------------------------------------------------------------
__global__ __launch_bounds__(256)
void head_kernel(const float* __restrict__ h,      // [E, 256]
                 const float* __restrict__ Wl,     // [256, 3]
                 const float* __restrict__ bl,     // [3]
                 float* __restrict__ out)          // [E, 3]
{
    const int warp = (blockIdx.x * blockDim.x + threadIdx.x) >> 5;
    const int lane = threadIdx.x & 31;
    if (warp >= EE) return;

    const float* hr = h + (size_t)warp * HID;
    float a0 = 0.f, a1 = 0.f, a2 = 0.f;
#pragma unroll
    for (int k = lane; k < HID; k += 32) {
        const float hv = hr[k];
        a0 = fmaf(hv, __ldg(&Wl[k * 3 + 0]), a0);
        a1 = fmaf(hv, __ldg(&Wl[k * 3 + 1]), a1);
        a2 = fmaf(hv, __ldg(&Wl[k * 3 + 2]), a2);
    }
#pragma unroll
    for (int o = 16; o > 0; o >>= 1) {
        a0 += __shfl_down_sync(0xFFFFFFFFu, a0, o);
        a1 += __shfl_down_sync(0xFFFFFFFFu, a1, o);
        a2 += __shfl_down_sync(0xFFFFFFFFu, a2, o);
    }
    if (lane == 0) {
        a0 += bl[0]; a1 += bl[1]; a2 += bl[2];
        const float m = fmaxf(a0, fmaxf(a1, a2));
        const float s = expf(a0 - m) + expf(a1 - m) + expf(a2 - m);
        const float ls = logf(s) + m;
        float* o = out + (size_t)warp * 3;
        o[0] = a0 - ls;
        o[1] = a1 - ls;
        o[2] = a2 - ls;
    }
}

// ---------------------------------------------------------------------------
// Launch
// ---------------------------------------------------------------------------
extern "C" void kernel_launch(void* const* d_in, const int* in_sizes, int n_in,
                              void* d_out, int out_size)
{
    const float* x     = (const float*)d_in[0];      // [N, 256]
    const int*   eidx  = (const int*)d_in[1];        // [2, E] int32
    const float* eattr = (const float*)d_in[2];      // [E, 16]
    const float* Wx    = (const float*)d_in[3];      // [256, 128]
    const float* bx    = (const float*)d_in[4];      // [128]
    const float* W0    = (const float*)d_in[5];      // [272, 256]
    const float* b0    = (const float*)d_in[6];      // [256]
    const float* Wm    = (const float*)d_in[7];      // [8, 256, 256]
    const float* bm    = (const float*)d_in[8];      // [8, 256]
    const float* Wl    = (const float*)d_in[9];      // [256, 3]
    const float* bl    = (const float*)d_in[10];     // [3]
    float*       out   = (float*)d_out;              // [E, 3]

    float *hnode, *hA, *hB;
    cudaGetSymbolAddress((void**)&hnode, g_hnode);
    cudaGetSymbolAddress((void**)&hA, g_hA);
    cudaGetSymbolAddress((void**)&hB, g_hB);

    // 1) node MLP: [N,256] @ [256,128] -> hnode [N,128]
    sgemm_bias_leaky<<<dim3(NN / 128, DIN / 128), 256>>>(
        x, Wx, bx, hnode, NN, DIN, DNODE);

    // 2) edge layer 0 (fused gather/concat): -> hA [E,256]
    edge0_gemm<<<dim3(EE / 128, HID / 128), 256>>>(
        hnode, eidx, eattr, W0, b0, hA);

    // 3) 8 mid layers, ping-pong hA <-> hB (ends in hA)
    for (int L = 0; L < 8; L++) {
        const float* src = (L & 1) ? hB : hA;
        float*       dst = (L & 1) ? hA : hB;
        sgemm_bias_leaky<<<dim3(EE / 128, HID / 128), 256>>>(
            src, Wm + (size_t)L * HID * HID, bm + (size_t)L * HID,
            dst, EE, HID, HID);
    }
    // after 8 layers result is in hA

    // 4) head: logits + log_softmax
    head_kernel<<<EE / 8, 256>>>(hA, Wl, bl, out);
}

// round 5
// speedup vs baseline: 2.4944x; 2.4944x over previous
#include <cuda_runtime.h>
#include <cuda_bf16.h>
#include <cstdint>

#define NEG_SLOPE 0.01f

// ---------------------------------------------------------------------------
// Problem constants
// ---------------------------------------------------------------------------
#define NN    65536
#define EE    262144
#define DIN   128
#define DNODE 256
#define DEDGE 272
#define HID   256
#define EA    16

// ---------------------------------------------------------------------------
// Scratch (device globals: allocation is forbidden)
// ---------------------------------------------------------------------------
static __device__ float g_hnode[(size_t)NN * DIN];                // 32 MB
static __device__ __nv_bfloat16 g_W0t_hi[HID * DEDGE];            // [n=256][k=272]
static __device__ __nv_bfloat16 g_W0t_lo[HID * DEDGE];
static __device__ __nv_bfloat16 g_Wmt_hi[8 * HID * HID];          // [L][n][k]
static __device__ __nv_bfloat16 g_Wmt_lo[8 * HID * HID];

__device__ __forceinline__ float lrelu(float v) {
    return v >= 0.0f ? v : NEG_SLOPE * v;
}

// ---------------------------------------------------------------------------
// Baseline-PTX tensor helpers (sm_80-level: valid on base sm_103 target)
// ---------------------------------------------------------------------------
__device__ __forceinline__ uint32_t smem_u32(const void* p) {
    uint32_t a;
    asm("{ .reg .u64 t; cvta.to.shared.u64 t, %1; cvt.u32.u64 %0, t; }"
        : "=r"(a) : "l"(p));
    return a;
}

__device__ __forceinline__ void ldsm_x4(uint32_t* r, uint32_t addr) {
    asm volatile("ldmatrix.sync.aligned.m8n8.x4.shared.b16 {%0,%1,%2,%3}, [%4];"
                 : "=r"(r[0]), "=r"(r[1]), "=r"(r[2]), "=r"(r[3]) : "r"(addr));
}

__device__ __forceinline__ void mma_bf16(float* d, const uint32_t* a,
                                         uint32_t b0, uint32_t b1) {
    asm volatile(
        "mma.sync.aligned.m16n8k16.row.col.f32.bf16.bf16.f32 "
        "{%0,%1,%2,%3}, {%4,%5,%6,%7}, {%8,%9}, {%0,%1,%2,%3};"
        : "+f"(d[0]), "+f"(d[1]), "+f"(d[2]), "+f"(d[3])
        : "r"(a[0]), "r"(a[1]), "r"(a[2]), "r"(a[3]), "r"(b0), "r"(b1));
}

__device__ __forceinline__ void cp_async16(uint32_t dst, const void* src) {
    asm volatile("cp.async.cg.shared.global [%0], [%1], 16;"
                 :: "r"(dst), "l"(src));
}
#define CP_COMMIT() asm volatile("cp.async.commit_group;")
#define CP_WAIT1()  asm volatile("cp.async.wait_group 1;")
#define CP_WAIT0()  asm volatile("cp.async.wait_group 0;")

// ---------------------------------------------------------------------------
// Weight prep: split fp32 -> bf16 hi/lo, transpose to [n][k]
// ---------------------------------------------------------------------------
__global__ __launch_bounds__(256)
void prep_w0(const float* __restrict__ W0,       // [272][256]
             __nv_bfloat16* __restrict__ Wh, __nv_bfloat16* __restrict__ Wl)
{
    int tid = blockIdx.x * 256 + threadIdx.x;    // 272*256
    if (tid >= DEDGE * HID) return;
    int k = tid >> 8, n = tid & 255;
    float w = W0[k * 256 + n];
    __nv_bfloat16 hi = __float2bfloat16(w);
    __nv_bfloat16 lo = __float2bfloat16(w - __bfloat162float(hi));
    Wh[n * DEDGE + k] = hi;
    Wl[n * DEDGE + k] = lo;
}

__global__ __launch_bounds__(256)
void prep_wmid(const float* __restrict__ Wm,     // [8][256][256] (k,n)
               __nv_bfloat16* __restrict__ Wh, __nv_bfloat16* __restrict__ Wl)
{
    int tid = blockIdx.x * 256 + threadIdx.x;    // 8*65536
    int L = tid >> 16, rem = tid & 0xFFFF;
    int k = rem >> 8, n = rem & 255;
    float w = Wm[(size_t)L * 65536 + k * 256 + n];
    __nv_bfloat16 hi = __float2bfloat16(w);
    __nv_bfloat16 lo = __float2bfloat16(w - __bfloat162float(hi));
    Wh[(size_t)L * 65536 + n * 256 + k] = hi;
    Wl[(size_t)L * 65536 + n * 256 + k] = lo;
}

// ---------------------------------------------------------------------------
// Node MLP SGEMM (fp32): hnode = leaky(x @ Wx + bx)
// ---------------------------------------------------------------------------
__global__ __launch_bounds__(256)
void sgemm_bias_leaky(const float* __restrict__ A, const float* __restrict__ B,
                      const float* __restrict__ bias, float* __restrict__ C,
                      int M, int N, int K)
{
    __shared__ float As[8][128];
    __shared__ float Bs[8][128];
    const int t = threadIdx.x;
    const int blockRow = blockIdx.x * 128;
    const int blockCol = blockIdx.y * 128;
    const int aRow = t >> 1, aK = (t & 1) * 4;
    const int bK = t >> 5,  bN = (t & 31) * 4;
    const int tr = t >> 4,  tc = t & 15;

    float acc[8][8];
#pragma unroll
    for (int i = 0; i < 8; i++)
#pragma unroll
        for (int j = 0; j < 8; j++) acc[i][j] = 0.0f;

    for (int k0 = 0; k0 < K; k0 += 8) {
        float4 av = *(const float4*)(A + (size_t)(blockRow + aRow) * K + k0 + aK);
        As[aK + 0][aRow] = av.x; As[aK + 1][aRow] = av.y;
        As[aK + 2][aRow] = av.z; As[aK + 3][aRow] = av.w;
        *(float4*)&Bs[bK][bN] =
            *(const float4*)(B + (size_t)(k0 + bK) * N + blockCol + bN);
        __syncthreads();
#pragma unroll
        for (int k = 0; k < 8; k++) {
            float ra[8], rb[8];
            *(float4*)&ra[0] = *(const float4*)&As[k][tr * 8];
            *(float4*)&ra[4] = *(const float4*)&As[k][tr * 8 + 4];
            *(float4*)&rb[0] = *(const float4*)&Bs[k][tc * 8];
            *(float4*)&rb[4] = *(const float4*)&Bs[k][tc * 8 + 4];
#pragma unroll
            for (int i = 0; i < 8; i++)
#pragma unroll
                for (int j = 0; j < 8; j++)
                    acc[i][j] = fmaf(ra[i], rb[j], acc[i][j]);
        }
        __syncthreads();
    }
#pragma unroll
    for (int i = 0; i < 8; i++) {
        const size_t rrow = (size_t)(blockRow + tr * 8 + i);
#pragma unroll
        for (int j = 0; j < 8; j += 4) {
            const int cc = blockCol + tc * 8 + j;
            float4 o;
            o.x = lrelu(acc[i][j + 0] + bias[cc + 0]);
            o.y = lrelu(acc[i][j + 1] + bias[cc + 1]);
            o.z = lrelu(acc[i][j + 2] + bias[cc + 2]);
            o.w = lrelu(acc[i][j + 3] + bias[cc + 3]);
            *(float4*)(C + rrow * N + cc) = o;
        }
    }
}

// ---------------------------------------------------------------------------
// Fused edge pipeline: gather -> edge0 -> 8 mid layers -> head+log_softmax
// CTA = 128 edges, 512 threads (16 warps, warp grid 4M x 4N, tile 32x64).
// Activations: SMEM bf16 hi/lo, stride 280 (conflict-free for ldmatrix).
// Weights: cp.async double-buffered K-chunks of 32 into [256][40] tiles.
// ---------------------------------------------------------------------------
#define STRA   280                       // A row stride in elems
#define A_HI_O 0
#define A_LO_O 71680                     // 128*280*2
#define W_OFF  143360
#define W_STG  40960                     // per stage: hi 20480 + lo 20480
#define IDX_O  225280                    // rs[128], cs[128]
#define SMEM_TOT 226304

__global__ __launch_bounds__(512, 1)
void edge_mlp_fused(const float* __restrict__ hnode,
                    const int* __restrict__ eidx,
                    const float* __restrict__ eattr,
                    const __nv_bfloat16* __restrict__ w0h,
                    const __nv_bfloat16* __restrict__ w0l,
                    const float* __restrict__ b0,
                    const __nv_bfloat16* __restrict__ wmh,
                    const __nv_bfloat16* __restrict__ wml,
                    const float* __restrict__ bm,
                    const float* __restrict__ Wlast,
                    const float* __restrict__ blast,
                    float* __restrict__ out)
{
    extern __shared__ char smem[];
    const uint32_t sb = smem_u32(smem);
    const int t = threadIdx.x;
    const int wid = t >> 5, lane = t & 31;
    const int wm = wid >> 2, wn = wid & 3;
    const int rowbase = blockIdx.x * 128;

    int* rs = (int*)(smem + IDX_O);
    int* cs = rs + 128;
    __nv_bfloat16* Ahi = (__nv_bfloat16*)(smem + A_HI_O);
    __nv_bfloat16* Alo = (__nv_bfloat16*)(smem + A_LO_O);

    // ---- gather + concat + hi/lo split -> A0 (K=272) ----
    if (t < 128) rs[t] = eidx[rowbase + t];
    else if (t < 256) cs[t - 128] = eidx[EE + rowbase + (t - 128)];
    __syncthreads();

    for (int idx = t; idx < 128 * 136; idx += 512) {
        const int row = idx / 136;
        const int k2 = (idx - row * 136) * 2;
        float2 v;
        if (k2 < 128)
            v = *(const float2*)(hnode + (size_t)rs[row] * DIN + k2);
        else if (k2 < 256)
            v = *(const float2*)(hnode + (size_t)cs[row] * DIN + (k2 - 128));
        else
            v = *(const float2*)(eattr + (size_t)(rowbase + row) * EA + (k2 - 256));
        __nv_bfloat16 h0 = __float2bfloat16(v.x);
        __nv_bfloat16 h1 = __float2bfloat16(v.y);
        __nv_bfloat16 l0 = __float2bfloat16(v.x - __bfloat162float(h0));
        __nv_bfloat16 l1 = __float2bfloat16(v.y - __bfloat162float(h1));
        __nv_bfloat162 ph; ph.x = h0; ph.y = h1;
        __nv_bfloat162 pl; pl.x = l0; pl.y = l1;
        *(__nv_bfloat162*)(Ahi + row * STRA + k2) = ph;
        *(__nv_bfloat162*)(Alo + row * STRA + k2) = pl;
    }
    __syncthreads();

    // ---- 9 GEMM layers ----
    for (int L = 0; L <= 8; L++) {
        const __nv_bfloat16 *Wh, *Wl;
        const float* bias;
        int K, ldW;
        if (L == 0) { Wh = w0h; Wl = w0l; bias = b0; K = DEDGE; ldW = DEDGE; }
        else {
            Wh = wmh + (size_t)(L - 1) * 65536;
            Wl = wml + (size_t)(L - 1) * 65536;
            bias = bm + (L - 1) * 256; K = 256; ldW = 256;
        }
        const int nk16 = K >> 4;                 // 17 or 16
        const int nchunk = (nk16 + 1) >> 1;      // 9 or 8

        float acc[2][8][4];
#pragma unroll
        for (int a = 0; a < 2; a++)
#pragma unroll
            for (int b = 0; b < 8; b++)
#pragma unroll
                for (int c = 0; c < 4; c++) acc[a][b][c] = 0.0f;

        // prefetch chunk 0
        {
            const int nc16 = (K - 0 >= 32) ? 4 : 2;
            const uint32_t dh = sb + W_OFF;
            const uint32_t dl = dh + 20480;
            for (int i = t; i < 256 * nc16; i += 512) {
                const int n = i / nc16, kk = i - n * nc16;
                cp_async16(dh + n * 80 + kk * 16, Wh + (size_t)n * ldW + kk * 8);
                cp_async16(dl + n * 80 + kk * 16, Wl + (size_t)n * ldW + kk * 8);
            }
            CP_COMMIT();
        }

        for (int c = 0; c < nchunk; c++) {
            if (c + 1 < nchunk) {
                const int k0 = (c + 1) * 32;
                const int nc16 = (K - k0 >= 32) ? 4 : 2;
                const uint32_t base = sb + W_OFF + ((c + 1) & 1) * W_STG;
                const uint32_t dl = base + 20480;
                for (int i = t; i < 256 * nc16; i += 512) {
                    const int n = i / nc16, kk = i - n * nc16;
                    cp_async16(base + n * 80 + kk * 16,
                               Wh + (size_t)n * ldW + k0 + kk * 8);
                    cp_async16(dl + n * 80 + kk * 16,
                               Wl + (size_t)n * ldW + k0 + kk * 8);
                }
                CP_COMMIT();
                CP_WAIT1();
            } else {
                CP_WAIT0();
            }
            __syncthreads();

            const uint32_t wbh = sb + W_OFF + (c & 1) * W_STG;
            const uint32_t wbl = wbh + 20480;
            const int steps = min(2, nk16 - c * 2);

            for (int s = 0; s < steps; s++) {
                const int kg = (c * 2 + s) * 16;   // A col
                const int kb = s * 16;             // W buffer col

                // A fragments (hi/lo) for 2 m-tiles
                uint32_t ah[2][4], al[2][4];
                const int r16 = lane & 15, khalf = lane >> 4;
#pragma unroll
                for (int mt = 0; mt < 2; mt++) {
                    const int row = wm * 32 + mt * 16 + r16;
                    const uint32_t off = (row * STRA + kg + khalf * 8) * 2;
                    ldsm_x4(ah[mt], sb + A_HI_O + off);
                    ldsm_x4(al[mt], sb + A_LO_O + off);
                }
                // B fragments per group of 2 n-tiles
                const int grp = lane >> 3, wi = lane & 7;
#pragma unroll
                for (int g = 0; g < 4; g++) {
                    const int nb = wn * 64 + g * 16;
                    const int n = nb + (grp >> 1) * 8 + wi;
                    const int kc = kb + (grp & 1) * 8;
                    const uint32_t boff = (uint32_t)(n * 40 + kc) * 2;
                    uint32_t bh[4], bl[4];
                    ldsm_x4(bh, wbh + boff);
                    ldsm_x4(bl, wbl + boff);
#pragma unroll
                    for (int mt = 0; mt < 2; mt++) {
#pragma unroll
                        for (int nt2 = 0; nt2 < 2; nt2++) {
                            float* d = acc[mt][g * 2 + nt2];
                            mma_bf16(d, ah[mt], bh[nt2 * 2], bh[nt2 * 2 + 1]);
                            mma_bf16(d, ah[mt], bl[nt2 * 2], bl[nt2 * 2 + 1]);
                            mma_bf16(d, al[mt], bh[nt2 * 2], bh[nt2 * 2 + 1]);
                        }
                    }
                }
            }
            __syncthreads();
        }

        // ---- epilogue: bias + leaky, write back hi/lo (in place) ----
#pragma unroll
        for (int mt = 0; mt < 2; mt++) {
            const int r0 = wm * 32 + mt * 16 + (lane >> 2);
#pragma unroll
            for (int nt = 0; nt < 8; nt++) {
                const int col = wn * 64 + nt * 8 + (lane & 3) * 2;
                const float bv0 = __ldg(&bias[col]);
                const float bv1 = __ldg(&bias[col + 1]);
#pragma unroll
                for (int h = 0; h < 2; h++) {      // rows r0, r0+8
                    const int row = r0 + h * 8;
                    const float v0 = lrelu(acc[mt][nt][h * 2 + 0] + bv0);
                    const float v1 = lrelu(acc[mt][nt][h * 2 + 1] + bv1);
                    __nv_bfloat16 h0 = __float2bfloat16(v0);
                    __nv_bfloat16 h1 = __float2bfloat16(v1);
                    __nv_bfloat16 l0 = __float2bfloat16(v0 - __bfloat162float(h0));
                    __nv_bfloat16 l1 = __float2bfloat16(v1 - __bfloat162float(h1));
                    __nv_bfloat162 ph; ph.x = h0; ph.y = h1;
                    __nv_bfloat162 pl; pl.x = l0; pl.y = l1;
                    *(__nv_bfloat162*)(Ahi + row * STRA + col) = ph;
                    *(__nv_bfloat162*)(Alo + row * STRA + col) = pl;
                }
            }
        }
        __syncthreads();
    }

    // ---- head: logits + log_softmax (warp -> 8 rows) ----
    for (int r = 0; r < 8; r++) {
        const int row = wid * 8 + r;
        float a0 = 0.f, a1 = 0.f, a2 = 0.f;
#pragma unroll
        for (int k = lane; k < 256; k += 32) {
            const float hv = __bfloat162float(Ahi[row * STRA + k]) +
                             __bfloat162float(Alo[row * STRA + k]);
            a0 = fmaf(hv, __ldg(&Wlast[k * 3 + 0]), a0);
            a1 = fmaf(hv, __ldg(&Wlast[k * 3 + 1]), a1);
            a2 = fmaf(hv, __ldg(&Wlast[k * 3 + 2]), a2);
        }
#pragma unroll
        for (int o = 16; o > 0; o >>= 1) {
            a0 += __shfl_down_sync(0xFFFFFFFFu, a0, o);
            a1 += __shfl_down_sync(0xFFFFFFFFu, a1, o);
            a2 += __shfl_down_sync(0xFFFFFFFFu, a2, o);
        }
        if (lane == 0) {
            a0 += __ldg(&blast[0]); a1 += __ldg(&blast[1]); a2 += __ldg(&blast[2]);
            const float m = fmaxf(a0, fmaxf(a1, a2));
            const float s = expf(a0 - m) + expf(a1 - m) + expf(a2 - m);
            const float ls = logf(s) + m;
            float* o = out + (size_t)(rowbase + row) * 3;
            o[0] = a0 - ls; o[1] = a1 - ls; o[2] = a2 - ls;
        }
    }
}

// ---------------------------------------------------------------------------
// Launch
// ---------------------------------------------------------------------------
extern "C" void kernel_launch(void* const* d_in, const int* in_sizes, int n_in,
                              void* d_out, int out_size)
{
    const float* x     = (const float*)d_in[0];
    const int*   eidx  = (const int*)d_in[1];
    const float* eattr = (const float*)d_in[2];
    const float* Wx    = (const float*)d_in[3];
    const float* bx    = (const float*)d_in[4];
    const float* W0    = (const float*)d_in[5];
    const float* b0    = (const float*)d_in[6];
    const float* Wm    = (const float*)d_in[7];
    const float* bm    = (const float*)d_in[8];
    const float* Wl    = (const float*)d_in[9];
    const float* bl    = (const float*)d_in[10];
    float*       out   = (float*)d_out;

    float* hnode;
    __nv_bfloat16 *w0h, *w0l, *wmh, *wml;
    cudaGetSymbolAddress((void**)&hnode, g_hnode);
    cudaGetSymbolAddress((void**)&w0h, g_W0t_hi);
    cudaGetSymbolAddress((void**)&w0l, g_W0t_lo);
    cudaGetSymbolAddress((void**)&wmh, g_Wmt_hi);
    cudaGetSymbolAddress((void**)&wml, g_Wmt_lo);

    cudaFuncSetAttribute(edge_mlp_fused,
                         cudaFuncAttributeMaxDynamicSharedMemorySize, SMEM_TOT);

    // weight prep
    prep_w0<<<(DEDGE * HID + 255) / 256, 256>>>(W0, w0h, w0l);
    prep_wmid<<<(8 * HID * HID) / 256, 256>>>(Wm, wmh, wml);

    // node MLP
    sgemm_bias_leaky<<<dim3(NN / 128, DIN / 128), 256>>>(
        x, Wx, bx, hnode, NN, DIN, DNODE);

    // fused edge pipeline
    edge_mlp_fused<<<EE / 128, 512, SMEM_TOT>>>(
        hnode, eidx, eattr, w0h, w0l, b0, wmh, wml, bm, Wl, bl, out);
}

// round 7
// speedup vs baseline: 2.9003x; 1.1627x over previous
#include <cuda_runtime.h>
#include <cuda_fp16.h>
#include <cstdint>

#define NEG_SLOPE 0.01f

// ---------------------------------------------------------------------------
// Problem constants
// ---------------------------------------------------------------------------
#define NN    65536
#define EE    262144
#define DIN   128
#define DNODE 256
#define DEDGE 272
#define HID   256
#define EA    16

// ---------------------------------------------------------------------------
// Scratch (device globals: allocation is forbidden)
// ---------------------------------------------------------------------------
static __device__ float g_hnode[(size_t)NN * DIN];        // 32 MB
static __device__ __half g_W0t_hi[HID * DEDGE];           // [n=256][k=272]
static __device__ __half g_W0t_lo[HID * DEDGE];
static __device__ __half g_Wmt_hi[8 * HID * HID];         // [L][n=256][k=256]
static __device__ __half g_Wmt_lo[8 * HID * HID];

__device__ __forceinline__ float lrelu(float v) {
    return v >= 0.0f ? v : NEG_SLOPE * v;
}

// ---------------------------------------------------------------------------
// Baseline-PTX helpers (sm_80-level, valid on base sm_103 target)
// ---------------------------------------------------------------------------
__device__ __forceinline__ uint32_t smem_u32(const void* p) {
    uint32_t a;
    asm("{ .reg .u64 t; cvta.to.shared.u64 t, %1; cvt.u32.u64 %0, t; }"
        : "=r"(a) : "l"(p));
    return a;
}

__device__ __forceinline__ void ldsm_x4(uint32_t* r, uint32_t addr) {
    asm volatile("ldmatrix.sync.aligned.m8n8.x4.shared.b16 {%0,%1,%2,%3}, [%4];"
                 : "=r"(r[0]), "=r"(r[1]), "=r"(r[2]), "=r"(r[3]) : "r"(addr));
}

__device__ __forceinline__ void mma_f16(float* d, const uint32_t* a,
                                        uint32_t b0, uint32_t b1) {
    asm volatile(
        "mma.sync.aligned.m16n8k16.row.col.f32.f16.f16.f32 "
        "{%0,%1,%2,%3}, {%4,%5,%6,%7}, {%8,%9}, {%0,%1,%2,%3};"
        : "+f"(d[0]), "+f"(d[1]), "+f"(d[2]), "+f"(d[3])
        : "r"(a[0]), "r"(a[1]), "r"(a[2]), "r"(a[3]), "r"(b0), "r"(b1));
}

__device__ __forceinline__ void cp_async16(uint32_t dst, const void* src) {
    asm volatile("cp.async.cg.shared.global [%0], [%1], 16;"
                 :: "r"(dst), "l"(src));
}
#define CP_COMMIT() asm volatile("cp.async.commit_group;")
#define CP_WAIT1()  asm volatile("cp.async.wait_group 1;")
#define CP_WAIT0()  asm volatile("cp.async.wait_group 0;")

// ---------------------------------------------------------------------------
// Weight prep: fp32 -> fp16 hi/lo, transpose to [n][k]
// ---------------------------------------------------------------------------
__global__ __launch_bounds__(256)
void prep_w0(const float* __restrict__ W0,       // [272][256]
             __half* __restrict__ Wh, __half* __restrict__ Wl)
{
    int tid = blockIdx.x * 256 + threadIdx.x;
    if (tid >= DEDGE * HID) return;
    int k = tid >> 8, n = tid & 255;
    float w = W0[k * 256 + n];
    __half hi = __float2half(w);
    __half lo = __float2half(w - __half2float(hi));
    Wh[n * DEDGE + k] = hi;
    Wl[n * DEDGE + k] = lo;
}

__global__ __launch_bounds__(256)
void prep_wmid(const float* __restrict__ Wm,     // [8][256 k][256 n]
               __half* __restrict__ Wh, __half* __restrict__ Wl)
{
    int tid = blockIdx.x * 256 + threadIdx.x;    // 8*65536
    int L = tid >> 16, rem = tid & 0xFFFF;
    int k = rem >> 8, n = rem & 255;
    float w = Wm[(size_t)L * 65536 + k * 256 + n];
    __half hi = __float2half(w);
    __half lo = __float2half(w - __half2float(hi));
    Wh[(size_t)L * 65536 + n * 256 + k] = hi;
    Wl[(size_t)L * 65536 + n * 256 + k] = lo;
}

// ---------------------------------------------------------------------------
// Node MLP SGEMM (fp32): hnode = leaky(x @ Wx + bx)
// ---------------------------------------------------------------------------
__global__ __launch_bounds__(256)
void sgemm_bias_leaky(const float* __restrict__ A, const float* __restrict__ B,
                      const float* __restrict__ bias, float* __restrict__ C,
                      int M, int N, int K)
{
    __shared__ float As[8][128];
    __shared__ float Bs[8][128];
    const int t = threadIdx.x;
    const int blockRow = blockIdx.x * 128;
    const int blockCol = blockIdx.y * 128;
    const int aRow = t >> 1, aK = (t & 1) * 4;
    const int bK = t >> 5,  bN = (t & 31) * 4;
    const int tr = t >> 4,  tc = t & 15;

    float acc[8][8];
#pragma unroll
    for (int i = 0; i < 8; i++)
#pragma unroll
        for (int j = 0; j < 8; j++) acc[i][j] = 0.0f;

    for (int k0 = 0; k0 < K; k0 += 8) {
        float4 av = *(const float4*)(A + (size_t)(blockRow + aRow) * K + k0 + aK);
        As[aK + 0][aRow] = av.x; As[aK + 1][aRow] = av.y;
        As[aK + 2][aRow] = av.z; As[aK + 3][aRow] = av.w;
        *(float4*)&Bs[bK][bN] =
            *(const float4*)(B + (size_t)(k0 + bK) * N + blockCol + bN);
        __syncthreads();
#pragma unroll
        for (int k = 0; k < 8; k++) {
            float ra[8], rb[8];
            *(float4*)&ra[0] = *(const float4*)&As[k][tr * 8];
            *(float4*)&ra[4] = *(const float4*)&As[k][tr * 8 + 4];
            *(float4*)&rb[0] = *(const float4*)&Bs[k][tc * 8];
            *(float4*)&rb[4] = *(const float4*)&Bs[k][tc * 8 + 4];
#pragma unroll
            for (int i = 0; i < 8; i++)
#pragma unroll
                for (int j = 0; j < 8; j++)
                    acc[i][j] = fmaf(ra[i], rb[j], acc[i][j]);
        }
        __syncthreads();
    }
#pragma unroll
    for (int i = 0; i < 8; i++) {
        const size_t rrow = (size_t)(blockRow + tr * 8 + i);
#pragma unroll
        for (int j = 0; j < 8; j += 4) {
            const int cc = blockCol + tc * 8 + j;
            float4 o;
            o.x = lrelu(acc[i][j + 0] + bias[cc + 0]);
            o.y = lrelu(acc[i][j + 1] + bias[cc + 1]);
            o.z = lrelu(acc[i][j + 2] + bias[cc + 2]);
            o.w = lrelu(acc[i][j + 3] + bias[cc + 3]);
            *(float4*)(C + rrow * N + cc) = o;
        }
    }
}

// ---------------------------------------------------------------------------
// Fused edge pipeline: gather -> edge0 -> 8 mid layers -> head+log_softmax
// CTA = 64 edges, 256 threads (8 warps, 2M x 4N, warp tile 32x64).
// 2 CTAs/SM. A: fp16 [64][280] (padded, conflict-free). W: fp16 hi/lo,
// double-buffered K-chunks of 32 with slot swizzle (k16 + (n>>1)) & 3.
// 2 MMA passes per k16: Ah*Wh + Ah*Wl.
// ---------------------------------------------------------------------------
#define STRA   280
#define A_O    0                         // 64*280*2 = 35840
#define W_O    35840                     // 2 stages x 32768
#define W_STG  32768
#define W_HALF 16384                     // lo offset within stage
#define IDX_O  101376                    // rs[64], cs[64]
#define SMEM_TOT 101888

__global__ __launch_bounds__(256, 2)
void edge_mlp_fused(const float* __restrict__ hnode,
                    const int* __restrict__ eidx,
                    const float* __restrict__ eattr,
                    const __half* __restrict__ w0h,
                    const __half* __restrict__ w0l,
                    const float* __restrict__ b0,
                    const __half* __restrict__ wmh,
                    const __half* __restrict__ wml,
                    const float* __restrict__ bm,
                    const float* __restrict__ Wlast,
                    const float* __restrict__ blast,
                    float* __restrict__ out)
{
    extern __shared__ char smem[];
    const uint32_t sb = smem_u32(smem);
    const int t = threadIdx.x;
    const int wid = t >> 5, lane = t & 31;
    const int wm = wid >> 2, wn = wid & 3;      // 2 x 4 warp grid
    const int rowbase = blockIdx.x * 64;

    int* rs = (int*)(smem + IDX_O);
    int* cs = rs + 64;
    __half* A = (__half*)(smem + A_O);

    // ---- gather + concat -> fp16 A0 (64 rows x K=272) ----
    if (t < 64) rs[t] = eidx[rowbase + t];
    else if (t < 128) cs[t - 64] = eidx[EE + rowbase + (t - 64)];
    __syncthreads();

    for (int idx = t; idx < 64 * 136; idx += 256) {
        const int row = idx / 136;
        const int k2 = (idx - row * 136) * 2;
        float2 v;
        if (k2 < 128)
            v = *(const float2*)(hnode + (size_t)rs[row] * DIN + k2);
        else if (k2 < 256)
            v = *(const float2*)(hnode + (size_t)cs[row] * DIN + (k2 - 128));
        else
            v = *(const float2*)(eattr + (size_t)(rowbase + row) * EA + (k2 - 256));
        __half2 p; p.x = __float2half(v.x); p.y = __float2half(v.y);
        *(__half2*)(A + row * STRA + k2) = p;
    }
    __syncthreads();

    // ---- 9 GEMM layers ----
    for (int L = 0; L <= 8; L++) {
        const __half *Wh, *Wl;
        const float* bias;
        int K, ldW;
        if (L == 0) { Wh = w0h; Wl = w0l; bias = b0; K = DEDGE; ldW = DEDGE; }
        else {
            Wh = wmh + (size_t)(L - 1) * 65536;
            Wl = wml + (size_t)(L - 1) * 65536;
            bias = bm + (L - 1) * 256; K = 256; ldW = 256;
        }
        const int nk16 = K >> 4;                 // 17 or 16
        const int nchunk = (nk16 + 1) >> 1;      // 9 or 8

        float acc[2][8][4];
#pragma unroll
        for (int a = 0; a < 2; a++)
#pragma unroll
            for (int b = 0; b < 8; b++)
#pragma unroll
                for (int c = 0; c < 4; c++) acc[a][b][c] = 0.0f;

        // prefetch chunk 0 (always 4 k16-units)
        {
            const uint32_t st = sb + W_O;
            for (int i = t; i < 2048; i += 256) {
                const int half = i >> 10;             // 0 hi, 1 lo
                const int j = i & 1023;
                const int n = j >> 2, u = j & 3;
                const __half* src = (half ? Wl : Wh) + (size_t)n * ldW + u * 8;
                cp_async16(st + half * W_HALF + n * 64 + (((u) + (n >> 1)) & 3) * 16,
                           src);
            }
            CP_COMMIT();
        }

        for (int c = 0; c < nchunk; c++) {
            if (c + 1 < nchunk) {
                const int k0 = (c + 1) * 32;
                const int nu = min(4, (K - k0) >> 3);   // 16B units this chunk
                const uint32_t st = sb + W_O + ((c + 1) & 1) * W_STG;
                const int tot = 256 * nu;
                for (int i = t; i < tot * 2; i += 256) {
                    const int half = (i >= tot) ? 1 : 0;
                    const int j = half ? i - tot : i;
                    const int n = j / nu, u = j - n * nu;
                    const __half* src = (half ? Wl : Wh) +
                                        (size_t)n * ldW + k0 + u * 8;
                    cp_async16(st + half * W_HALF + n * 64 +
                                   (((u) + (n >> 1)) & 3) * 16,
                               src);
                }
                CP_COMMIT();
                CP_WAIT1();
            } else {
                CP_WAIT0();
            }
            __syncthreads();

            const uint32_t wbh = sb + W_O + (c & 1) * W_STG;
            const uint32_t wbl = wbh + W_HALF;
            const int steps = min(2, nk16 - c * 2);

            for (int s = 0; s < steps; s++) {
                const int kg = (c * 2 + s) * 16;

                // A fragments for 2 m-tiles
                uint32_t ah[2][4];
                const int r16 = lane & 15, khalf = lane >> 4;
#pragma unroll
                for (int mt = 0; mt < 2; mt++) {
                    const int row = wm * 32 + mt * 16 + r16;
                    ldsm_x4(ah[mt], sb + A_O +
                            (uint32_t)(row * STRA + kg + khalf * 8) * 2);
                }
                const int grp = lane >> 3, wi = lane & 7;
                const int u16 = 2 * s + (grp & 1);
#pragma unroll
                for (int g = 0; g < 4; g++) {
                    const int n = wn * 64 + g * 16 + (grp >> 1) * 8 + wi;
                    const uint32_t boff =
                        (uint32_t)(n * 64 + ((u16 + (n >> 1)) & 3) * 16);
                    uint32_t bh[4], bl[4];
                    ldsm_x4(bh, wbh + boff);
                    ldsm_x4(bl, wbl + boff);
#pragma unroll
                    for (int mt = 0; mt < 2; mt++) {
#pragma unroll
                        for (int nt2 = 0; nt2 < 2; nt2++) {
                            float* d = acc[mt][g * 2 + nt2];
                            mma_f16(d, ah[mt], bh[nt2 * 2], bh[nt2 * 2 + 1]);
                            mma_f16(d, ah[mt], bl[nt2 * 2], bl[nt2 * 2 + 1]);
                        }
                    }
                }
            }
            __syncthreads();
        }

        // ---- epilogue: bias + leaky -> fp16 A (in place) ----
#pragma unroll
        for (int mt = 0; mt < 2; mt++) {
            const int r0 = wm * 32 + mt * 16 + (lane >> 2);
#pragma unroll
            for (int nt = 0; nt < 8; nt++) {
                const int col = wn * 64 + nt * 8 + (lane & 3) * 2;
                const float bv0 = __ldg(&bias[col]);
                const float bv1 = __ldg(&bias[col + 1]);
#pragma unroll
                for (int h = 0; h < 2; h++) {
                    const int row = r0 + h * 8;
                    const float v0 = lrelu(acc[mt][nt][h * 2 + 0] + bv0);
                    const float v1 = lrelu(acc[mt][nt][h * 2 + 1] + bv1);
                    __half2 p; p.x = __float2half(v0); p.y = __float2half(v1);
                    *(__half2*)(A + row * STRA + col) = p;
                }
            }
        }
        __syncthreads();
    }

    // ---- head: logits + log_softmax (each warp -> 8 rows) ----
    for (int r = 0; r < 8; r++) {
        const int row = wid * 8 + r;
        float a0 = 0.f, a1 = 0.f, a2 = 0.f;
#pragma unroll
        for (int k = lane; k < 256; k += 32) {
            const float hv = __half2float(A[row * STRA + k]);
            a0 = fmaf(hv, __ldg(&Wlast[k * 3 + 0]), a0);
            a1 = fmaf(hv, __ldg(&Wlast[k * 3 + 1]), a1);
            a2 = fmaf(hv, __ldg(&Wlast[k * 3 + 2]), a2);
        }
#pragma unroll
        for (int o = 16; o > 0; o >>= 1) {
            a0 += __shfl_down_sync(0xFFFFFFFFu, a0, o);
            a1 += __shfl_down_sync(0xFFFFFFFFu, a1, o);
            a2 += __shfl_down_sync(0xFFFFFFFFu, a2, o);
        }
        if (lane == 0) {
            a0 += __ldg(&blast[0]); a1 += __ldg(&blast[1]); a2 += __ldg(&blast[2]);
            const float m = fmaxf(a0, fmaxf(a1, a2));
            const float s = expf(a0 - m) + expf(a1 - m) + expf(a2 - m);
            const float ls = logf(s) + m;
            float* o = out + (size_t)(rowbase + row) * 3;
            o[0] = a0 - ls; o[1] = a1 - ls; o[2] = a2 - ls;
        }
    }
}

// ---------------------------------------------------------------------------
// Launch
// ---------------------------------------------------------------------------
extern "C" void kernel_launch(void* const* d_in, const int* in_sizes, int n_in,
                              void* d_out, int out_size)
{
    const float* x     = (const float*)d_in[0];
    const int*   eidx  = (const int*)d_in[1];
    const float* eattr = (const float*)d_in[2];
    const float* Wx    = (const float*)d_in[3];
    const float* bx    = (const float*)d_in[4];
    const float* W0    = (const float*)d_in[5];
    const float* b0    = (const float*)d_in[6];
    const float* Wm    = (const float*)d_in[7];
    const float* bm    = (const float*)d_in[8];
    const float* Wl    = (const float*)d_in[9];
    const float* bl    = (const float*)d_in[10];
    float*       out   = (float*)d_out;

    float* hnode;
    __half *w0h, *w0l, *wmh, *wml;
    cudaGetSymbolAddress((void**)&hnode, g_hnode);
    cudaGetSymbolAddress((void**)&w0h, g_W0t_hi);
    cudaGetSymbolAddress((void**)&w0l, g_W0t_lo);
    cudaGetSymbolAddress((void**)&wmh, g_Wmt_hi);
    cudaGetSymbolAddress((void**)&wml, g_Wmt_lo);

    cudaFuncSetAttribute(edge_mlp_fused,
                         cudaFuncAttributeMaxDynamicSharedMemorySize, SMEM_TOT);

    // weight prep
    prep_w0<<<(DEDGE * HID + 255) / 256, 256>>>(W0, w0h, w0l);
    prep_wmid<<<(8 * HID * HID) / 256, 256>>>(Wm, wmh, wml);

    // node MLP
    sgemm_bias_leaky<<<dim3(NN / 128, DIN / 128), 256>>>(
        x, Wx, bx, hnode, NN, DIN, DNODE);

    // fused edge pipeline (64 edges/CTA, 2 CTAs/SM)
    edge_mlp_fused<<<EE / 64, 256, SMEM_TOT>>>(
        hnode, eidx, eattr, w0h, w0l, b0, wmh, wml, bm, Wl, bl, out);
}

// round 9
// speedup vs baseline: 7.5757x; 2.6120x over previous
#include <cuda_runtime.h>
#include <cuda_fp16.h>
#include <cstdint>

#define NEG_SLOPE 0.01f

// ---------------------------------------------------------------------------
// Problem constants
// ---------------------------------------------------------------------------
#define NN    65536
#define EE    262144
#define DIN   128
#define DNODE 256
#define DEDGE 272
#define HID   256
#define EA    16

// ---------------------------------------------------------------------------
// Scratch (device globals: allocation is forbidden)
// ---------------------------------------------------------------------------
static __device__ float g_hnode[(size_t)NN * DIN];        // 32 MB
static __device__ __half g_W0t[HID * DEDGE];              // [n=256][k=272]
static __device__ __half g_Wmt[8 * HID * HID];            // [L][n=256][k=256]

__device__ __forceinline__ float lrelu(float v) {
    return v >= 0.0f ? v : NEG_SLOPE * v;
}

// ---------------------------------------------------------------------------
// Baseline-PTX helpers (sm_80-level, valid on base sm_103 target)
// ---------------------------------------------------------------------------
__device__ __forceinline__ uint32_t smem_u32(const void* p) {
    uint32_t a;
    asm("{ .reg .u64 t; cvta.to.shared.u64 t, %1; cvt.u32.u64 %0, t; }"
        : "=r"(a) : "l"(p));
    return a;
}

__device__ __forceinline__ void ldsm_x4(uint32_t* r, uint32_t addr) {
    asm volatile("ldmatrix.sync.aligned.m8n8.x4.shared.b16 {%0,%1,%2,%3}, [%4];"
                 : "=r"(r[0]), "=r"(r[1]), "=r"(r[2]), "=r"(r[3]) : "r"(addr));
}

__device__ __forceinline__ void mma_f16(float* d, const uint32_t* a,
                                        uint32_t b0, uint32_t b1) {
    asm volatile(
        "mma.sync.aligned.m16n8k16.row.col.f32.f16.f16.f32 "
        "{%0,%1,%2,%3}, {%4,%5,%6,%7}, {%8,%9}, {%0,%1,%2,%3};"
        : "+f"(d[0]), "+f"(d[1]), "+f"(d[2]), "+f"(d[3])
        : "r"(a[0]), "r"(a[1]), "r"(a[2]), "r"(a[3]), "r"(b0), "r"(b1));
}

__device__ __forceinline__ void cp_async16(uint32_t dst, const void* src) {
    asm volatile("cp.async.cg.shared.global [%0], [%1], 16;"
                 :: "r"(dst), "l"(src));
}
#define CP_COMMIT() asm volatile("cp.async.commit_group;")
#define CP_WAIT1()  asm volatile("cp.async.wait_group 1;")
#define CP_WAIT0()  asm volatile("cp.async.wait_group 0;")

// ---------------------------------------------------------------------------
// Weight prep: fp32 -> fp16, transpose to [n][k]
// ---------------------------------------------------------------------------
__global__ __launch_bounds__(256)
void prep_w0(const float* __restrict__ W0, __half* __restrict__ Wt)
{
    int tid = blockIdx.x * 256 + threadIdx.x;
    if (tid >= DEDGE * HID) return;
    int k = tid >> 8, n = tid & 255;
    Wt[n * DEDGE + k] = __float2half(W0[k * 256 + n]);
}

__global__ __launch_bounds__(256)
void prep_wmid(const float* __restrict__ Wm, __half* __restrict__ Wt)
{
    int tid = blockIdx.x * 256 + threadIdx.x;    // 8*65536
    int L = tid >> 16, rem = tid & 0xFFFF;
    int k = rem >> 8, n = rem & 255;
    Wt[(size_t)L * 65536 + n * 256 + k] = __float2half(Wm[(size_t)L * 65536 + k * 256 + n]);
}

// ---------------------------------------------------------------------------
// Node MLP SGEMM (fp32): hnode = leaky(x @ Wx + bx)
// ---------------------------------------------------------------------------
__global__ __launch_bounds__(256)
void sgemm_bias_leaky(const float* __restrict__ A, const float* __restrict__ B,
                      const float* __restrict__ bias, float* __restrict__ C,
                      int M, int N, int K)
{
    __shared__ float As[8][128];
    __shared__ float Bs[8][128];
    const int t = threadIdx.x;
    const int blockRow = blockIdx.x * 128;
    const int blockCol = blockIdx.y * 128;
    const int aRow = t >> 1, aK = (t & 1) * 4;
    const int bK = t >> 5,  bN = (t & 31) * 4;
    const int tr = t >> 4,  tc = t & 15;

    float acc[8][8];
#pragma unroll
    for (int i = 0; i < 8; i++)
#pragma unroll
        for (int j = 0; j < 8; j++) acc[i][j] = 0.0f;

    for (int k0 = 0; k0 < K; k0 += 8) {
        float4 av = *(const float4*)(A + (size_t)(blockRow + aRow) * K + k0 + aK);
        As[aK + 0][aRow] = av.x; As[aK + 1][aRow] = av.y;
        As[aK + 2][aRow] = av.z; As[aK + 3][aRow] = av.w;
        *(float4*)&Bs[bK][bN] =
            *(const float4*)(B + (size_t)(k0 + bK) * N + blockCol + bN);
        __syncthreads();
#pragma unroll
        for (int k = 0; k < 8; k++) {
            float ra[8], rb[8];
            *(float4*)&ra[0] = *(const float4*)&As[k][tr * 8];
            *(float4*)&ra[4] = *(const float4*)&As[k][tr * 8 + 4];
            *(float4*)&rb[0] = *(const float4*)&Bs[k][tc * 8];
            *(float4*)&rb[4] = *(const float4*)&Bs[k][tc * 8 + 4];
#pragma unroll
            for (int i = 0; i < 8; i++)
#pragma unroll
                for (int j = 0; j < 8; j++)
                    acc[i][j] = fmaf(ra[i], rb[j], acc[i][j]);
        }
        __syncthreads();
    }
#pragma unroll
    for (int i = 0; i < 8; i++) {
        const size_t rrow = (size_t)(blockRow + tr * 8 + i);
#pragma unroll
        for (int j = 0; j < 8; j += 4) {
            const int cc = blockCol + tc * 8 + j;
            float4 o;
            o.x = lrelu(acc[i][j + 0] + bias[cc + 0]);
            o.y = lrelu(acc[i][j + 1] + bias[cc + 1]);
            o.z = lrelu(acc[i][j + 2] + bias[cc + 2]);
            o.w = lrelu(acc[i][j + 3] + bias[cc + 3]);
            *(float4*)(C + rrow * N + cc) = o;
        }
    }
}

// ---------------------------------------------------------------------------
// Fused edge pipeline. CTA = 64 edges, 256 threads (8 warps, 2M x 4N),
// 2 CTAs/SM. A: fp16 [64][280]. W: fp16 single, 3-stage cp.async pipeline,
// K-chunks of 32, XOR slot swizzle (u ^ ((n>>1)&3)). 1 MMA pass per k16.
// ---------------------------------------------------------------------------
#define STRA   280
#define A_O    0                          // 64*280*2 = 35840
#define W_O    35840                      // 3 stages x 16384 = 49152
#define W_STG  16384
#define IDX_O  84992                      // rs[64], cs[64]
#define SMEM_TOT 85504

// One GEMM layer: A[64 x KEL] (SMEM fp16) @ W^T  -> leaky(+bias) -> A in place
template<int KEL>
__device__ __forceinline__ void gemm_layer(
    uint32_t sb, __half* __restrict__ A,
    const __half* __restrict__ W, const float* __restrict__ bias,
    int t, int lane, int wm, int wn,
    uint32_t aB0, uint32_t aB1, const uint32_t* __restrict__ bC)
{
    constexpr int NK16 = KEL / 16;            // 17 or 16
    constexpr int NCH  = (NK16 + 1) / 2;      // 9 or 8

    float acc[2][8][4];
#pragma unroll
    for (int a = 0; a < 2; a++)
#pragma unroll
        for (int b = 0; b < 8; b++)
#pragma unroll
            for (int c = 0; c < 4; c++) acc[a][b][c] = 0.0f;

    // ---- prologue: prefetch chunks 0, 1 ----
#pragma unroll
    for (int pc = 0; pc < 2; pc++) {
        const int k0 = pc * 32;
        const int nu = ((KEL - k0) >= 32) ? 4 : ((KEL - k0) >> 3);
        const uint32_t st = sb + W_O + pc * W_STG;
#pragma unroll
        for (int i = 0; i < nu; i++) {
            const int j = t + i * 256;
            const int n = (nu == 4) ? (j >> 2) : (j >> 1);
            const int u = (nu == 4) ? (j & 3) : (j & 1);
            cp_async16(st + n * 64 + ((u ^ ((n >> 1) & 3)) << 4),
                       W + (size_t)n * KEL + k0 + u * 8);
        }
        CP_COMMIT();
    }

#pragma unroll
    for (int c = 0; c < NCH; c++) {
        if (c + 1 < NCH) { CP_WAIT1(); } else { CP_WAIT0(); }
        __syncthreads();

        // prefetch chunk c+2 into stage (c+2)%3
        if (c + 2 < NCH) {
            const int k0 = (c + 2) * 32;
            const int nu = ((KEL - k0) >= 32) ? 4 : ((KEL - k0) >> 3);
            const uint32_t st = sb + W_O + ((c + 2) % 3) * W_STG;
#pragma unroll
            for (int i = 0; i < nu; i++) {
                const int j = t + i * 256;
                const int n = (nu == 4) ? (j >> 2) : (j >> 1);
                const int u = (nu == 4) ? (j & 3) : (j & 1);
                cp_async16(st + n * 64 + ((u ^ ((n >> 1) & 3)) << 4),
                           W + (size_t)n * KEL + k0 + u * 8);
            }
            CP_COMMIT();
        }

        // ---- compute chunk c ----
        const uint32_t wst = sb + W_O + (c % 3) * W_STG;
        const int steps = (NK16 - 2 * c >= 2) ? 2 : 1;
#pragma unroll
        for (int s = 0; s < steps; s++) {
            const int kgB = (2 * c + s) * 32;   // A byte offset for this k16
            uint32_t af[2][4];
            ldsm_x4(af[0], aB0 + kgB);
            ldsm_x4(af[1], aB1 + kgB);
            const uint32_t sbit = (uint32_t)(s << 5);
#pragma unroll
            for (int g = 0; g < 4; g++) {
                uint32_t bf[4];
                ldsm_x4(bf, wst + (bC[g] ^ sbit));
#pragma unroll
                for (int mt = 0; mt < 2; mt++) {
                    mma_f16(acc[mt][g * 2 + 0], af[mt], bf[0], bf[1]);
                    mma_f16(acc[mt][g * 2 + 1], af[mt], bf[2], bf[3]);
                }
            }
        }
    }
    __syncthreads();   // all ldsm reads of A done before epilogue overwrites

    // ---- epilogue: bias + leaky -> fp16 A (in place) ----
#pragma unroll
    for (int mt = 0; mt < 2; mt++) {
        const int r0 = wm * 32 + mt * 16 + (lane >> 2);
#pragma unroll
        for (int nt = 0; nt < 8; nt++) {
            const int col = wn * 64 + nt * 8 + (lane & 3) * 2;
            const float bv0 = __ldg(&bias[col]);
            const float bv1 = __ldg(&bias[col + 1]);
#pragma unroll
            for (int h = 0; h < 2; h++) {
                const int row = r0 + h * 8;
                const float v0 = lrelu(acc[mt][nt][h * 2 + 0] + bv0);
                const float v1 = lrelu(acc[mt][nt][h * 2 + 1] + bv1);
                __half2 p; p.x = __float2half(v0); p.y = __float2half(v1);
                *(__half2*)(A + row * STRA + col) = p;
            }
        }
    }
    __syncthreads();
}

__global__ __launch_bounds__(256, 2)
void edge_mlp_fused(const float* __restrict__ hnode,
                    const int* __restrict__ eidx,
                    const float* __restrict__ eattr,
                    const __half* __restrict__ w0,
                    const float* __restrict__ b0,
                    const __half* __restrict__ wm_,
                    const float* __restrict__ bm,
                    const float* __restrict__ Wlast,
                    const float* __restrict__ blast,
                    float* __restrict__ out)
{
    extern __shared__ char smem[];
    const uint32_t sb = smem_u32(smem);
    const int t = threadIdx.x;
    const int wid = t >> 5, lane = t & 31;
    const int wm = wid >> 2, wn = wid & 3;      // 2 x 4 warp grid
    const int rowbase = blockIdx.x * 64;

    int* rs = (int*)(smem + IDX_O);
    int* cs = rs + 64;
    __half* A = (__half*)(smem + A_O);

    // ---- per-warp ldmatrix base addresses (layer-invariant) ----
    const int r16 = lane & 15, khalf = lane >> 4;
    const uint32_t aB0 = sb + A_O +
        (uint32_t)(((wm * 32 + r16) * STRA + khalf * 8) * 2);
    const uint32_t aB1 = aB0 + 16 * STRA * 2;
    const int grp = lane >> 3, wi = lane & 7;
    uint32_t bC[4];
#pragma unroll
    for (int g = 0; g < 4; g++) {
        const int n = wn * 64 + g * 16 + (grp >> 1) * 8 + wi;
        const uint32_t sn = (uint32_t)((n >> 1) & 3);
        bC[g] = ((uint32_t)(n * 64) | (sn << 4)) ^ ((uint32_t)(grp & 1) << 4);
    }

    // ---- gather + concat -> fp16 A0 (64 rows x 272) ----
    if (t < 64) rs[t] = eidx[rowbase + t];
    else if (t < 128) cs[t - 64] = eidx[EE + rowbase + (t - 64)];
    __syncthreads();

#pragma unroll
    for (int it = 0; it < 16; it++) {          // hnode[row] -> cols 0..127
        const int i = t + it * 256;
        const int row = i >> 6, k2 = (i & 63) * 2;
        float2 v = *(const float2*)(hnode + (size_t)rs[row] * DIN + k2);
        __half2 p; p.x = __float2half(v.x); p.y = __float2half(v.y);
        *(__half2*)(A + row * STRA + k2) = p;
    }
#pragma unroll
    for (int it = 0; it < 16; it++) {          // hnode[col] -> cols 128..255
        const int i = t + it * 256;
        const int row = i >> 6, k2 = (i & 63) * 2;
        float2 v = *(const float2*)(hnode + (size_t)cs[row] * DIN + k2);
        __half2 p; p.x = __float2half(v.x); p.y = __float2half(v.y);
        *(__half2*)(A + row * STRA + 128 + k2) = p;
    }
#pragma unroll
    for (int it = 0; it < 2; it++) {           // eattr -> cols 256..271
        const int i = t + it * 256;
        const int row = i >> 3, k2 = (i & 7) * 2;
        float2 v = *(const float2*)(eattr + (size_t)(rowbase + row) * EA + k2);
        __half2 p; p.x = __float2half(v.x); p.y = __float2half(v.y);
        *(__half2*)(A + row * STRA + 256 + k2) = p;
    }
    __syncthreads();

    // ---- 9 GEMM layers ----
    gemm_layer<DEDGE>(sb, A, w0, b0, t, lane, wm, wn, aB0, aB1, bC);
#pragma unroll 1
    for (int L = 0; L < 8; L++)
        gemm_layer<HID>(sb, A, wm_ + (size_t)L * 65536, bm + L * 256,
                        t, lane, wm, wn, aB0, aB1, bC);

    // ---- head: logits + log_softmax (each warp -> 8 rows) ----
    for (int r = 0; r < 8; r++) {
        const int row = wid * 8 + r;
        float a0 = 0.f, a1 = 0.f, a2 = 0.f;
#pragma unroll
        for (int k = lane; k < 256; k += 32) {
            const float hv = __half2float(A[row * STRA + k]);
            a0 = fmaf(hv, __ldg(&Wlast[k * 3 + 0]), a0);
            a1 = fmaf(hv, __ldg(&Wlast[k * 3 + 1]), a1);
            a2 = fmaf(hv, __ldg(&Wlast[k * 3 + 2]), a2);
        }
#pragma unroll
        for (int o = 16; o > 0; o >>= 1) {
            a0 += __shfl_down_sync(0xFFFFFFFFu, a0, o);
            a1 += __shfl_down_sync(0xFFFFFFFFu, a1, o);
            a2 += __shfl_down_sync(0xFFFFFFFFu, a2, o);
        }
        if (lane == 0) {
            a0 += __ldg(&blast[0]); a1 += __ldg(&blast[1]); a2 += __ldg(&blast[2]);
            const float m = fmaxf(a0, fmaxf(a1, a2));
            const float s = expf(a0 - m) + expf(a1 - m) + expf(a2 - m);
            const float ls = logf(s) + m;
            float* o = out + (size_t)(rowbase + row) * 3;
            o[0] = a0 - ls; o[1] = a1 - ls; o[2] = a2 - ls;
        }
    }
}

// ---------------------------------------------------------------------------
// Launch
// ---------------------------------------------------------------------------
extern "C" void kernel_launch(void* const* d_in, const int* in_sizes, int n_in,
                              void* d_out, int out_size)
{
    const float* x     = (const float*)d_in[0];
    const int*   eidx  = (const int*)d_in[1];
    const float* eattr = (const float*)d_in[2];
    const float* Wx    = (const float*)d_in[3];
    const float* bx    = (const float*)d_in[4];
    const float* W0    = (const float*)d_in[5];
    const float* b0    = (const float*)d_in[6];
    const float* Wm    = (const float*)d_in[7];
    const float* bm    = (const float*)d_in[8];
    const float* Wl    = (const float*)d_in[9];
    const float* bl    = (const float*)d_in[10];
    float*       out   = (float*)d_out;

    float* hnode;
    __half *w0t, *wmt;
    cudaGetSymbolAddress((void**)&hnode, g_hnode);
    cudaGetSymbolAddress((void**)&w0t, g_W0t);
    cudaGetSymbolAddress((void**)&wmt, g_Wmt);

    cudaFuncSetAttribute(edge_mlp_fused,
                         cudaFuncAttributeMaxDynamicSharedMemorySize, SMEM_TOT);

    // weight prep
    prep_w0<<<(DEDGE * HID + 255) / 256, 256>>>(W0, w0t);
    prep_wmid<<<(8 * HID * HID) / 256, 256>>>(Wm, wmt);

    // node MLP
    sgemm_bias_leaky<<<dim3(NN / 128, DIN / 128), 256>>>(
        x, Wx, bx, hnode, NN, DIN, DNODE);

    // fused edge pipeline (64 edges/CTA, 2 CTAs/SM)
    edge_mlp_fused<<<EE / 64, 256, SMEM_TOT>>>(
        hnode, eidx, eattr, w0t, b0, wmt, bm, Wl, bl, out);
}

// round 10
// speedup vs baseline: 8.7907x; 1.1604x over previous
#include <cuda_runtime.h>
#include <cuda_fp16.h>
#include <cstdint>

#define NEG_SLOPE 0.01f

// ---------------------------------------------------------------------------
// Problem constants
// ---------------------------------------------------------------------------
#define NN    65536
#define EE    262144
#define DIN   128
#define DNODE 256
#define DEDGE 272
#define HID   256
#define EA    16

// ---------------------------------------------------------------------------
// Scratch (device globals: allocation is forbidden)
// ---------------------------------------------------------------------------
static __device__ __half g_hnodeH[(size_t)NN * DIN];      // 16 MB (fp16 node feats)
static __device__ __half g_W0t[HID * DEDGE];              // [n=256][k=272]
static __device__ __half g_Wmt[8 * HID * HID];            // [L][n=256][k=256]
static __device__ __half g_Wxt[DIN * DNODE];              // [n=128][k=256]

__device__ __forceinline__ float lrelu(float v) {
    return v >= 0.0f ? v : NEG_SLOPE * v;
}

// ---------------------------------------------------------------------------
// Baseline-PTX helpers (sm_80-level, valid on base sm_103 target)
// ---------------------------------------------------------------------------
__device__ __forceinline__ uint32_t smem_u32(const void* p) {
    uint32_t a;
    asm("{ .reg .u64 t; cvta.to.shared.u64 t, %1; cvt.u32.u64 %0, t; }"
        : "=r"(a) : "l"(p));
    return a;
}

__device__ __forceinline__ void ldsm_x4(uint32_t* r, uint32_t addr) {
    asm volatile("ldmatrix.sync.aligned.m8n8.x4.shared.b16 {%0,%1,%2,%3}, [%4];"
                 : "=r"(r[0]), "=r"(r[1]), "=r"(r[2]), "=r"(r[3]) : "r"(addr));
}

__device__ __forceinline__ void mma_f16(float* d, const uint32_t* a,
                                        uint32_t b0, uint32_t b1) {
    asm volatile(
        "mma.sync.aligned.m16n8k16.row.col.f32.f16.f16.f32 "
        "{%0,%1,%2,%3}, {%4,%5,%6,%7}, {%8,%9}, {%0,%1,%2,%3};"
        : "+f"(d[0]), "+f"(d[1]), "+f"(d[2]), "+f"(d[3])
        : "r"(a[0]), "r"(a[1]), "r"(a[2]), "r"(a[3]), "r"(b0), "r"(b1));
}

__device__ __forceinline__ void cp_async16(uint32_t dst, const void* src) {
    asm volatile("cp.async.cg.shared.global [%0], [%1], 16;"
                 :: "r"(dst), "l"(src));
}
#define CP_COMMIT() asm volatile("cp.async.commit_group;")
#define CP_WAIT0()  asm volatile("cp.async.wait_group 0;")

// ---------------------------------------------------------------------------
// Weight prep: fp32 -> fp16, transpose to [n][k]
// ---------------------------------------------------------------------------
__global__ __launch_bounds__(256)
void prep_w0(const float* __restrict__ W0, __half* __restrict__ Wt)
{
    int tid = blockIdx.x * 256 + threadIdx.x;
    if (tid >= DEDGE * HID) return;
    int k = tid >> 8, n = tid & 255;
    Wt[n * DEDGE + k] = __float2half(W0[k * 256 + n]);
}

__global__ __launch_bounds__(256)
void prep_wmid(const float* __restrict__ Wm, __half* __restrict__ Wt)
{
    int tid = blockIdx.x * 256 + threadIdx.x;    // 8*65536
    int L = tid >> 16, rem = tid & 0xFFFF;
    int k = rem >> 8, n = rem & 255;
    Wt[(size_t)L * 65536 + n * 256 + k] =
        __float2half(Wm[(size_t)L * 65536 + k * 256 + n]);
}

__global__ __launch_bounds__(256)
void prep_wx(const float* __restrict__ Wx, __half* __restrict__ Wt)
{
    int tid = blockIdx.x * 256 + threadIdx.x;    // 256*128
    if (tid >= DNODE * DIN) return;
    int k = tid >> 7, n = tid & 127;
    Wt[n * DNODE + k] = __float2half(Wx[k * DIN + n]);
}

// ---------------------------------------------------------------------------
// SMEM geometry (shared by node + fused kernels)
// A: fp16 [rows][280];  W chunk: [n][8 x 16B slots], slot = u ^ (n & 7)
// ---------------------------------------------------------------------------
#define STRA   280
#define A_O    0                          // 64*280*2 = 35840
#define W_O    35840
#define W_STG  32768                      // 256 n x 128 B
#define IDX_O  101376                     // rs[64], cs[64]
#define SMEM_TOT 101888                   // fused kernel
#define NODE_SMEM (35840 + 65536)         // node kernel: A + 4 x 16KB W chunks

// ---------------------------------------------------------------------------
// Node MLP on HMMA: hnodeH = fp16(leaky(x @ Wx + bx))
// CTA = 64 rows, 256 threads (8 warps, 2M x 4N, warp tile 32x32).
// Full W (128n x 256k = 64 KB) loaded once; one sync; 16 k16 steps.
// ---------------------------------------------------------------------------
__global__ __launch_bounds__(256, 2)
void node_hmma(const float* __restrict__ x,
               const __half* __restrict__ Wxt,     // [128][256]
               const float* __restrict__ bx,
               __half* __restrict__ hnodeH)
{
    extern __shared__ char smem[];
    const uint32_t sb = smem_u32(smem);
    const int t = threadIdx.x;
    const int wid = t >> 5, lane = t & 31;
    const int wm = wid >> 2, wn = wid & 3;
    const int rowbase = blockIdx.x * 64;
    __half* A = (__half*)(smem + A_O);

    // A: 64 x 256 fp32 -> fp16  (float4 -> 2x half2)
#pragma unroll
    for (int i = 0; i < 16; i++) {
        const int j = t + i * 256;                 // 0..4095
        const int row = j >> 6, k4 = (j & 63) * 4;
        float4 v = *(const float4*)(x + (size_t)(rowbase + row) * DNODE + k4);
        __half2 p0; p0.x = __float2half(v.x); p0.y = __float2half(v.y);
        __half2 p1; p1.x = __float2half(v.z); p1.y = __float2half(v.w);
        *(__half2*)(A + row * STRA + k4) = p0;
        *(__half2*)(A + row * STRA + k4 + 2) = p1;
    }
    // W: 4 chunks x [128n][64k]
#pragma unroll
    for (int i = 0; i < 16; i++) {
        const int j = t + i * 256;                 // 0..4095
        const int ch = j >> 10, r = j & 1023;
        const int n = r >> 3, u = r & 7;
        cp_async16(sb + W_O + ch * 16384 + n * 128 + ((u ^ (n & 7)) << 4),
                   Wxt + (size_t)n * DNODE + ch * 64 + u * 8);
    }
    CP_COMMIT();
    CP_WAIT0();
    __syncthreads();

    const int r16 = lane & 15, khalf = lane >> 4;
    const uint32_t aB0 = sb + A_O +
        (uint32_t)(((wm * 32 + r16) * STRA + khalf * 8) * 2);
    const uint32_t aB1 = aB0 + 16 * STRA * 2;
    const int grp = lane >> 3, wi = lane & 7;
    uint32_t bC[2];
#pragma unroll
    for (int g = 0; g < 2; g++) {
        const int n = wn * 32 + g * 16 + (grp >> 1) * 8 + wi;
        bC[g] = (uint32_t)(n * 128) + ((((uint32_t)(grp & 1)) ^ (n & 7)) << 4);
    }

    float acc[2][4][4];
#pragma unroll
    for (int a = 0; a < 2; a++)
#pragma unroll
        for (int b = 0; b < 4; b++)
#pragma unroll
            for (int c = 0; c < 4; c++) acc[a][b][c] = 0.0f;

#pragma unroll
    for (int kg = 0; kg < 16; kg++) {
        uint32_t af[2][4];
        ldsm_x4(af[0], aB0 + kg * 32);
        ldsm_x4(af[1], aB1 + kg * 32);
        const uint32_t wst = sb + W_O + (kg >> 2) * 16384;
        const uint32_t sbit = (uint32_t)((kg & 3) << 5);
#pragma unroll
        for (int g = 0; g < 2; g++) {
            uint32_t bf[4];
            ldsm_x4(bf, wst + (bC[g] ^ sbit));
#pragma unroll
            for (int mt = 0; mt < 2; mt++) {
                mma_f16(acc[mt][g * 2 + 0], af[mt], bf[0], bf[1]);
                mma_f16(acc[mt][g * 2 + 1], af[mt], bf[2], bf[3]);
            }
        }
    }

    // epilogue -> global fp16
#pragma unroll
    for (int mt = 0; mt < 2; mt++) {
        const int r0 = wm * 32 + mt * 16 + (lane >> 2);
#pragma unroll
        for (int nt = 0; nt < 4; nt++) {
            const int col = wn * 32 + nt * 8 + (lane & 3) * 2;
            const float bv0 = __ldg(&bx[col]);
            const float bv1 = __ldg(&bx[col + 1]);
#pragma unroll
            for (int h = 0; h < 2; h++) {
                const int row = r0 + h * 8;
                const float v0 = lrelu(acc[mt][nt][h * 2 + 0] + bv0);
                const float v1 = lrelu(acc[mt][nt][h * 2 + 1] + bv1);
                __half2 p; p.x = __float2half(v0); p.y = __float2half(v1);
                *(__half2*)(hnodeH + (size_t)(rowbase + row) * DIN + col) = p;
            }
        }
    }
}

// ---------------------------------------------------------------------------
// One fused GEMM layer: A[64 x KEL] @ W^T -> leaky(+bias) -> A in place.
// K-chunks of 64 (2-stage cp.async, 1 sync per chunk).
// ---------------------------------------------------------------------------
template<int KEL>
__device__ __forceinline__ void gemm_layer(
    uint32_t sb, __half* __restrict__ A,
    const __half* __restrict__ W, const float* __restrict__ bias,
    int t, int lane, int wm, int wn,
    uint32_t aB0, uint32_t aB1, const uint32_t* __restrict__ bC)
{
    constexpr int NK16 = KEL / 16;            // 17 or 16
    constexpr int NCH  = (NK16 + 3) / 4;      // 5 or 4

    float acc[2][8][4];
#pragma unroll
    for (int a = 0; a < 2; a++)
#pragma unroll
        for (int b = 0; b < 8; b++)
#pragma unroll
            for (int c = 0; c < 4; c++) acc[a][b][c] = 0.0f;

    // prologue: prefetch chunk 0 (always full: 8 units/row)
    {
        const uint32_t st = sb + W_O;
#pragma unroll
        for (int i = 0; i < 8; i++) {
            const int j = t + i * 256;
            const int n = j >> 3, u = j & 7;
            cp_async16(st + n * 128 + ((u ^ (n & 7)) << 4),
                       W + (size_t)n * KEL + u * 8);
        }
        CP_COMMIT();
    }

#pragma unroll
    for (int c = 0; c < NCH; c++) {
        CP_WAIT0();
        __syncthreads();          // chunk c ready; all warps done with chunk c-1

        if (c + 1 < NCH) {        // prefetch chunk c+1 into other stage
            const int k0 = (c + 1) * 64;
            const int nu = ((KEL - k0) >= 64) ? 8 : ((KEL - k0) >> 3);
            const uint32_t st = sb + W_O + ((c + 1) & 1) * W_STG;
#pragma unroll
            for (int i = 0; i < nu; i++) {
                const int j = t + i * 256;
                const int n = (nu == 8) ? (j >> 3) : (j >> 1);
                const int u = (nu == 8) ? (j & 7) : (j & 1);
                cp_async16(st + n * 128 + ((u ^ (n & 7)) << 4),
                           W + (size_t)n * KEL + k0 + u * 8);
            }
            CP_COMMIT();
        }

        // compute chunk c (up to 4 k16 steps)
        const uint32_t wst = sb + W_O + (c & 1) * W_STG;
        const int ks = (NK16 - 4 * c >= 4) ? 4 : (NK16 - 4 * c);
#pragma unroll
        for (int s = 0; s < ks; s++) {
            const int kg = c * 4 + s;
            uint32_t af[2][4];
            ldsm_x4(af[0], aB0 + kg * 32);
            ldsm_x4(af[1], aB1 + kg * 32);
            const uint32_t sbit = (uint32_t)(s << 5);
#pragma unroll
            for (int g = 0; g < 4; g++) {
                uint32_t bf[4];
                ldsm_x4(bf, wst + (bC[g] ^ sbit));
#pragma unroll
                for (int mt = 0; mt < 2; mt++) {
                    mma_f16(acc[mt][g * 2 + 0], af[mt], bf[0], bf[1]);
                    mma_f16(acc[mt][g * 2 + 1], af[mt], bf[2], bf[3]);
                }
            }
        }
    }
    __syncthreads();   // all ldsm reads of A done before epilogue overwrites

    // epilogue: bias + leaky -> fp16 A (in place)
#pragma unroll
    for (int mt = 0; mt < 2; mt++) {
        const int r0 = wm * 32 + mt * 16 + (lane >> 2);
#pragma unroll
        for (int nt = 0; nt < 8; nt++) {
            const int col = wn * 64 + nt * 8 + (lane & 3) * 2;
            const float bv0 = __ldg(&bias[col]);
            const float bv1 = __ldg(&bias[col + 1]);
#pragma unroll
            for (int h = 0; h < 2; h++) {
                const int row = r0 + h * 8;
                const float v0 = lrelu(acc[mt][nt][h * 2 + 0] + bv0);
                const float v1 = lrelu(acc[mt][nt][h * 2 + 1] + bv1);
                __half2 p; p.x = __float2half(v0); p.y = __float2half(v1);
                *(__half2*)(A + row * STRA + col) = p;
            }
        }
    }
    __syncthreads();
}

// ---------------------------------------------------------------------------
// Fused edge pipeline. CTA = 64 edges, 256 threads (8 warps, 2M x 4N),
// 2 CTAs/SM.
// ---------------------------------------------------------------------------
__global__ __launch_bounds__(256, 2)
void edge_mlp_fused(const __half* __restrict__ hnodeH,
                    const int* __restrict__ eidx,
                    const float* __restrict__ eattr,
                    const __half* __restrict__ w0,
                    const float* __restrict__ b0,
                    const __half* __restrict__ wm_,
                    const float* __restrict__ bm,
                    const float* __restrict__ Wlast,
                    const float* __restrict__ blast,
                    float* __restrict__ out)
{
    extern __shared__ char smem[];
    const uint32_t sb = smem_u32(smem);
    const int t = threadIdx.x;
    const int wid = t >> 5, lane = t & 31;
    const int wm = wid >> 2, wn = wid & 3;
    const int rowbase = blockIdx.x * 64;

    int* rs = (int*)(smem + IDX_O);
    int* cs = rs + 64;
    __half* A = (__half*)(smem + A_O);

    // layer-invariant ldmatrix bases
    const int r16 = lane & 15, khalf = lane >> 4;
    const uint32_t aB0 = sb + A_O +
        (uint32_t)(((wm * 32 + r16) * STRA + khalf * 8) * 2);
    const uint32_t aB1 = aB0 + 16 * STRA * 2;
    const int grp = lane >> 3, wi = lane & 7;
    uint32_t bC[4];
#pragma unroll
    for (int g = 0; g < 4; g++) {
        const int n = wn * 64 + g * 16 + (grp >> 1) * 8 + wi;
        bC[g] = (uint32_t)(n * 128) + ((((uint32_t)(grp & 1)) ^ (n & 7)) << 4);
    }

    // ---- gather + concat -> fp16 A0 (64 rows x 272) ----
    if (t < 64) rs[t] = eidx[rowbase + t];
    else if (t < 128) cs[t - 64] = eidx[EE + rowbase + (t - 64)];
    __syncthreads();

#pragma unroll
    for (int it = 0; it < 8; it++) {          // hnodeH[row] -> cols 0..127
        const int i = t + it * 256;
        const int row = i >> 5, k4 = (i & 31) * 4;
        uint2 v = *(const uint2*)(hnodeH + (size_t)rs[row] * DIN + k4);
        *(uint2*)(A + row * STRA + k4) = v;
    }
#pragma unroll
    for (int it = 0; it < 8; it++) {          // hnodeH[col] -> cols 128..255
        const int i = t + it * 256;
        const int row = i >> 5, k4 = (i & 31) * 4;
        uint2 v = *(const uint2*)(hnodeH + (size_t)cs[row] * DIN + k4);
        *(uint2*)(A + row * STRA + 128 + k4) = v;
    }
#pragma unroll
    for (int it = 0; it < 2; it++) {          // eattr -> cols 256..271
        const int i = t + it * 256;
        const int row = i >> 3, k2 = (i & 7) * 2;
        float2 v = *(const float2*)(eattr + (size_t)(rowbase + row) * EA + k2);
        __half2 p; p.x = __float2half(v.x); p.y = __float2half(v.y);
        *(__half2*)(A + row * STRA + 256 + k2) = p;
    }
    __syncthreads();

    // ---- 9 GEMM layers ----
    gemm_layer<DEDGE>(sb, A, w0, b0, t, lane, wm, wn, aB0, aB1, bC);
#pragma unroll 1
    for (int L = 0; L < 8; L++)
        gemm_layer<HID>(sb, A, wm_ + (size_t)L * 65536, bm + L * 256,
                        t, lane, wm, wn, aB0, aB1, bC);

    // ---- head: logits + log_softmax (each warp -> 8 rows) ----
    for (int r = 0; r < 8; r++) {
        const int row = wid * 8 + r;
        float a0 = 0.f, a1 = 0.f, a2 = 0.f;
#pragma unroll
        for (int k = lane; k < 256; k += 32) {
            const float hv = __half2float(A[row * STRA + k]);
            a0 = fmaf(hv, __ldg(&Wlast[k * 3 + 0]), a0);
            a1 = fmaf(hv, __ldg(&Wlast[k * 3 + 1]), a1);
            a2 = fmaf(hv, __ldg(&Wlast[k * 3 + 2]), a2);
        }
#pragma unroll
        for (int o = 16; o > 0; o >>= 1) {
            a0 += __shfl_down_sync(0xFFFFFFFFu, a0, o);
            a1 += __shfl_down_sync(0xFFFFFFFFu, a1, o);
            a2 += __shfl_down_sync(0xFFFFFFFFu, a2, o);
        }
        if (lane == 0) {
            a0 += __ldg(&blast[0]); a1 += __ldg(&blast[1]); a2 += __ldg(&blast[2]);
            const float m = fmaxf(a0, fmaxf(a1, a2));
            const float s = expf(a0 - m) + expf(a1 - m) + expf(a2 - m);
            const float ls = logf(s) + m;
            float* o = out + (size_t)(rowbase + row) * 3;
            o[0] = a0 - ls; o[1] = a1 - ls; o[2] = a2 - ls;
        }
    }
}

// ---------------------------------------------------------------------------
// Launch
// ---------------------------------------------------------------------------
extern "C" void kernel_launch(void* const* d_in, const int* in_sizes, int n_in,
                              void* d_out, int out_size)
{
    const float* x     = (const float*)d_in[0];
    const int*   eidx  = (const int*)d_in[1];
    const float* eattr = (const float*)d_in[2];
    const float* Wx    = (const float*)d_in[3];
    const float* bx    = (const float*)d_in[4];
    const float* W0    = (const float*)d_in[5];
    const float* b0    = (const float*)d_in[6];
    const float* Wm    = (const float*)d_in[7];
    const float* bm    = (const float*)d_in[8];
    const float* Wl    = (const float*)d_in[9];
    const float* bl    = (const float*)d_in[10];
    float*       out   = (float*)d_out;

    __half *hnodeH, *w0t, *wmt, *wxt;
    cudaGetSymbolAddress((void**)&hnodeH, g_hnodeH);
    cudaGetSymbolAddress((void**)&w0t, g_W0t);
    cudaGetSymbolAddress((void**)&wmt, g_Wmt);
    cudaGetSymbolAddress((void**)&wxt, g_Wxt);

    cudaFuncSetAttribute(edge_mlp_fused,
                         cudaFuncAttributeMaxDynamicSharedMemorySize, SMEM_TOT);
    cudaFuncSetAttribute(node_hmma,
                         cudaFuncAttributeMaxDynamicSharedMemorySize, NODE_SMEM);

    // weight prep
    prep_w0<<<(DEDGE * HID + 255) / 256, 256>>>(W0, w0t);
    prep_wmid<<<(8 * HID * HID) / 256, 256>>>(Wm, wmt);
    prep_wx<<<(DNODE * DIN + 255) / 256, 256>>>(Wx, wxt);

    // node MLP on tensor cores -> fp16 node features
    node_hmma<<<NN / 64, 256, NODE_SMEM>>>(x, wxt, bx, hnodeH);

    // fused edge pipeline (64 edges/CTA, 2 CTAs/SM)
    edge_mlp_fused<<<EE / 64, 256, SMEM_TOT>>>(
        hnodeH, eidx, eattr, w0t, b0, wmt, bm, Wl, bl, out);
}